// round 10
// baseline (speedup 1.0000x reference)
#include <cuda_runtime.h>
#include <cuda_fp16.h>
#include <cstdint>
#include <cstddef>

// Shape: B=2,S=2048 -> T=4096 tokens, D=1024, W=4096, SLOT=8, 8 leaves.
#define T_TOK   4096
#define DIM     1024
#define NW      4096
#define NSLOT   8
#define NLEAF   8

// Scratch (device globals; no allocation allowed)
__device__ __align__(1024) __half g_basis_h[(size_t)T_TOK * 16];      // slots,1,0...
__device__ __align__(1024) __half g_selB_h[(size_t)NLEAF * NW * 16];  // per-leaf sel rows
__device__ __align__(1024) __half g_roots_h[(size_t)T_TOK * NW];      // 32 MB
__device__ __align__(1024) __half g_outwT_h[(size_t)DIM * NW];        // 8 MB

// ---------------------------------------------------------------------------
__device__ __forceinline__ uint32_t tanh_f16x2(uint32_t x) {
    uint32_t y;
    asm("tanh.approx.f16x2 %0, %1;" : "=r"(y) : "r"(x));
    return y;
}
__device__ __forceinline__ uint32_t hfma2_u(uint32_t a, uint32_t b, uint32_t c) {
    uint32_t d;
    asm("fma.rn.f16x2 %0, %1, %2, %3;" : "=r"(d) : "r"(a), "r"(b), "r"(c));
    return d;
}
__device__ __forceinline__ uint32_t pack_h2(float lo, float hi) {
    __half2 h = __floats2half2_rn(lo, hi);
    return *(uint32_t*)&h;
}
__device__ __forceinline__ uint32_t smem_u32(const void* p) {
    uint32_t a;
    asm("{ .reg .u64 t; cvta.to.shared.u64 t, %1; cvt.u32.u64 %0, t; }" : "=r"(a) : "l"(p));
    return a;
}

// ---------------------------------------------------------------------------
// Kernel A: basis[t] = [tanh(hidden@slot_w+b) (8), 1.0, 0 x7] as fp16.
__global__ __launch_bounds__(128) void slots_kernel(
    const float* __restrict__ hidden,
    const float* __restrict__ slot_w,
    const float* __restrict__ slot_b)
{
    int t = blockIdx.x;
    const float* h = hidden + (size_t)t * DIM;
    float acc[NSLOT];
#pragma unroll
    for (int s = 0; s < NSLOT; ++s) acc[s] = 0.0f;

#pragma unroll
    for (int it = 0; it < 2; ++it) {
        int d = threadIdx.x * 4 + it * 512;
        float4 hv = *(const float4*)(h + d);
#pragma unroll
        for (int j = 0; j < 4; ++j) {
            float hx = (j == 0) ? hv.x : (j == 1) ? hv.y : (j == 2) ? hv.z : hv.w;
            const float* wr = slot_w + (size_t)(d + j) * NSLOT;
            float4 w0 = *(const float4*)(wr);
            float4 w1 = *(const float4*)(wr + 4);
            acc[0] = fmaf(hx, w0.x, acc[0]);
            acc[1] = fmaf(hx, w0.y, acc[1]);
            acc[2] = fmaf(hx, w0.z, acc[2]);
            acc[3] = fmaf(hx, w0.w, acc[3]);
            acc[4] = fmaf(hx, w1.x, acc[4]);
            acc[5] = fmaf(hx, w1.y, acc[5]);
            acc[6] = fmaf(hx, w1.z, acc[6]);
            acc[7] = fmaf(hx, w1.w, acc[7]);
        }
    }

#pragma unroll
    for (int s = 0; s < NSLOT; ++s) {
        float v = acc[s];
#pragma unroll
        for (int off = 16; off; off >>= 1)
            v += __shfl_xor_sync(0xffffffffu, v, off);
        acc[s] = v;
    }

    __shared__ float red[4][NSLOT];
    int lane = threadIdx.x & 31, warp = threadIdx.x >> 5;
    if (lane == 0) {
#pragma unroll
        for (int s = 0; s < NSLOT; ++s) red[warp][s] = acc[s];
    }
    __syncthreads();
    if (threadIdx.x < 16) {
        int s = threadIdx.x;
        __half o;
        if (s < NSLOT) {
            float v = red[0][s] + red[1][s] + red[2][s] + red[3][s] + slot_b[s];
            o = __float2half_rn(tanhf(v));
        } else if (s == 8) {
            o = __float2half_rn(1.0f);
        } else {
            o = __float2half_rn(0.0f);
        }
        g_basis_h[(size_t)t * 16 + s] = o;
    }
}

// ---------------------------------------------------------------------------
// Kernel B: softmax over 11 logits -> g_selB_h[l][w][16] fp16:
// [sel0..sel7, sel10-sel8, 0 x7]  (basis consts are -1,0,1)
__global__ __launch_bounds__(256) void softmax_kernel(const float* __restrict__ logits)
{
    int r = blockIdx.x * blockDim.x + threadIdx.x;   // w*8 + l
    if (r >= NW * NLEAF) return;
    int w = r >> 3, l = r & 7;
    const float* row = logits + (size_t)r * 11;
    float x[11];
    float m = -1e30f;
#pragma unroll
    for (int c = 0; c < 11; ++c) { x[c] = row[c]; m = fmaxf(m, x[c]); }
    float sum = 0.0f;
#pragma unroll
    for (int c = 0; c < 11; ++c) { x[c] = __expf(x[c] - m); sum += x[c]; }
    float inv = 1.0f / sum;

    __half2* dst = (__half2*)(g_selB_h + ((size_t)l * NW + w) * 16);
#pragma unroll
    for (int c = 0; c < 4; ++c)
        dst[c] = __floats2half2_rn(x[2 * c] * inv, x[2 * c + 1] * inv);
    dst[4] = __floats2half2_rn((x[10] - x[8]) * inv, 0.0f);
    __half2 z = __floats2half2_rn(0.0f, 0.0f);
    dst[5] = z; dst[6] = z; dst[7] = z;
}

// ---------------------------------------------------------------------------
// Kernel T: g_outwT_h[d][w] = half(out_w[w][d])
__global__ __launch_bounds__(256) void transpose_kernel(const float* __restrict__ Wm)
{
    __shared__ float t[32][33];
    int wt = blockIdx.x, dt = blockIdx.y;
    int tx = threadIdx.x & 31, ty = threadIdx.x >> 5;   // 32 x 8
#pragma unroll
    for (int i = 0; i < 4; ++i) {
        int w = wt * 32 + ty + i * 8;
        t[ty + i * 8][tx] = Wm[(size_t)w * DIM + dt * 32 + tx];
    }
    __syncthreads();
#pragma unroll
    for (int i = 0; i < 4; ++i) {
        int d = dt * 32 + ty + i * 8;
        g_outwT_h[(size_t)d * NW + wt * 32 + tx] = __float2half_rn(t[tx][ty + i * 8]);
    }
}

// ---------------------------------------------------------------------------
// Kernel C: leaf einsum via mma.sync (K=16) + half2 tree reduce.
// CTA: 32 tokens x 64 w, 8 warps, warp tile 16 tok x 16 w.
__global__ __launch_bounds__(256) void roots_mma_kernel(const float* __restrict__ node_params)
{
    __shared__ __align__(16) char sAraw[32 * 32];          // 32 tok rows x 32B
    __shared__ __align__(16) char sBraw[8 * 64 * 32];      // [leaf][w] rows x 32B

    const int tid  = threadIdx.x;
    const int lane = tid & 31;
    const int wid  = tid >> 5;
    const int warp_m = wid & 1;         // token tile (16 each)
    const int warp_n = wid >> 1;        // w tile (16 each)
    const int bt = blockIdx.y * 32;
    const int bw = blockIdx.x * 64;

    const uint32_t uA = smem_u32(sAraw);
    const uint32_t uB = smem_u32(sBraw);

    // ---- fill sA: 64 chunks of 16B, swizzle c ^ ((row>>2)&1)
    if (tid < 64) {
        int row = tid >> 1, c = tid & 1;
        const uint4 v = *(const uint4*)(g_basis_h + (size_t)(bt + row) * 16 + c * 8);
        *(uint4*)(sAraw + row * 32 + ((c ^ ((row >> 2) & 1)) << 4)) = v;
    }
    // ---- fill sB: 1024 chunks, 4 per thread
#pragma unroll
    for (int j = 0; j < 4; ++j) {
        int id = tid + 256 * j;
        int l = id >> 7, w = (id >> 1) & 63, c = id & 1;
        const uint4 v = *(const uint4*)(g_selB_h + ((size_t)l * NW + bw + w) * 16 + c * 8);
        *(uint4*)(sBraw + l * 2048 + w * 32 + ((c ^ ((w >> 2) & 1)) << 4)) = v;
    }
    __syncthreads();

    // ---- A fragment (m16 x k16)
    uint32_t a[4];
    {
        int row = warp_m * 16 + ((lane >> 3) & 1) * 8 + (lane & 7);
        int kc  = lane >> 4;
        uint32_t addr = uA + row * 32 + ((kc ^ ((row >> 2) & 1)) << 4);
        asm volatile("ldmatrix.sync.aligned.m8n8.x4.shared.b16 {%0,%1,%2,%3}, [%4];"
                     : "=r"(a[0]), "=r"(a[1]), "=r"(a[2]), "=r"(a[3]) : "r"(addr));
    }

    float acc[2][8][4];
#pragma unroll
    for (int nt = 0; nt < 2; ++nt)
#pragma unroll
        for (int l = 0; l < 8; ++l)
#pragma unroll
            for (int i = 0; i < 4; ++i) acc[nt][l][i] = 0.0f;

    // ---- per-leaf B fragment + 2 MMAs
    {
        int n  = warp_n * 16 + ((lane >> 4) & 1) * 8 + (lane & 7);
        int kc = (lane >> 3) & 1;
        uint32_t baddr = uB + n * 32 + ((kc ^ ((n >> 2) & 1)) << 4);
#pragma unroll
        for (int l = 0; l < 8; ++l) {
            uint32_t b0, b1, b2, b3;
            asm volatile("ldmatrix.sync.aligned.m8n8.x4.shared.b16 {%0,%1,%2,%3}, [%4];"
                         : "=r"(b0), "=r"(b1), "=r"(b2), "=r"(b3)
                         : "r"(baddr + l * 2048));
            asm volatile(
                "mma.sync.aligned.m16n8k16.row.col.f32.f16.f16.f32 "
                "{%0,%1,%2,%3}, {%4,%5,%6,%7}, {%8,%9}, {%0,%1,%2,%3};"
                : "+f"(acc[0][l][0]), "+f"(acc[0][l][1]), "+f"(acc[0][l][2]), "+f"(acc[0][l][3])
                : "r"(a[0]), "r"(a[1]), "r"(a[2]), "r"(a[3]), "r"(b0), "r"(b1));
            asm volatile(
                "mma.sync.aligned.m16n8k16.row.col.f32.f16.f16.f32 "
                "{%0,%1,%2,%3}, {%4,%5,%6,%7}, {%8,%9}, {%0,%1,%2,%3};"
                : "+f"(acc[1][l][0]), "+f"(acc[1][l][1]), "+f"(acc[1][l][2]), "+f"(acc[1][l][3])
                : "r"(a[0]), "r"(a[1]), "r"(a[2]), "r"(a[3]), "r"(b2), "r"(b3));
        }
    }

    // ---- half2 tree reduce: pairs (c0,c1) and (c2,c3) per nt.
    // node: z = L*(pw*R+la) + (ra*R+nb);  x = tanh(z)   [3 HFMA2 + 1 MUFU]
    float lw = __ldg(node_params + 0), rw = __ldg(node_params + 1);
    float pw = __ldg(node_params + 2), dw = __ldg(node_params + 3);
    float nb = __ldg(node_params + 4);
    float la = lw + dw, ra = rw - dw;
    const uint32_t la2 = pack_h2(la, la), ra2 = pack_h2(ra, ra);
    const uint32_t pw2 = pack_h2(pw, pw), nb2 = pack_h2(nb, nb);

    const int g = lane >> 2, cq = lane & 3;

#pragma unroll
    for (int nt = 0; nt < 2; ++nt) {
        uint32_t rootp[2];
#pragma unroll
        for (int pr = 0; pr < 2; ++pr) {               // pr=0:(c0,c1)  pr=1:(c2,c3)
            uint32_t x[8];
#pragma unroll
            for (int l = 0; l < 8; ++l)
                x[l] = pack_h2(acc[nt][l][2 * pr], acc[nt][l][2 * pr + 1]);
#pragma unroll
            for (int d = 0; d < 3; ++d) {
                int n = NLEAF >> (d + 1);
#pragma unroll
                for (int i = 0; i < 4; ++i) {
                    if (i < n) {
                        uint32_t L = x[2 * i], R = x[2 * i + 1];
                        x[i] = tanh_f16x2(hfma2_u(L, hfma2_u(pw2, R, la2),
                                                  hfma2_u(ra2, R, nb2)));
                    }
                }
            }
            rootp[pr] = x[0];
        }
        int col = bw + warp_n * 16 + nt * 8 + 2 * cq;
        int r0  = bt + warp_m * 16 + g;
        *(uint32_t*)(g_roots_h + (size_t)r0 * NW + col)       = rootp[0];
        *(uint32_t*)(g_roots_h + (size_t)(r0 + 8) * NW + col) = rootp[1];
    }
}

// ---------------------------------------------------------------------------
// Kernel D: fp16 mma.sync GEMM, BK=64 (3 stages x 32KB = 96KB smem).
#define BM 128
#define BN 128
#define BK 64
#define KTILES (NW / BK)                  // 64
#define ROWB (BK * 2)                     // 128 bytes/row
#define ASTG (BM * ROWB)                  // 16384
#define BSTG (BN * ROWB)                  // 16384
#define STG_BYTES (ASTG + BSTG)           // 32768
#define GSTAGES 3
#define GEMM_SMEM (GSTAGES * STG_BYTES)   // 98304

__device__ __forceinline__ void cp_async16(uint32_t dst, const void* src) {
    asm volatile("cp.async.cg.shared.global [%0], [%1], 16;" :: "r"(dst), "l"(src));
}

__global__ __launch_bounds__(256, 2) void gemm_mma_kernel(
    const float* __restrict__ bias, float* __restrict__ C)
{
    extern __shared__ char smem[];
    const uint32_t sbase = smem_u32(smem);

    const int tid  = threadIdx.x;
    const int lane = tid & 31;
    const int wid  = tid >> 5;
    const int warp_m = wid >> 1;
    const int warp_n = wid & 1;
    const int bm = blockIdx.y * BM;
    const int bn = blockIdx.x * BN;

    const __half* Ah = g_roots_h;
    const __half* Bh = g_outwT_h;

    uint32_t dA[4], dB[4];
    const __half* sA[4];
    const __half* sB[4];
#pragma unroll
    for (int j = 0; j < 4; ++j) {
        int id  = tid + 256 * j;          // 0..1023
        int row = id >> 3, c = id & 7;
        int sw  = c ^ (row & 7);
        dA[j] = sbase + row * ROWB + sw * 16;
        dB[j] = sbase + ASTG + row * ROWB + sw * 16;
        sA[j] = Ah + (size_t)(bm + row) * NW + c * 8;
        sB[j] = Bh + (size_t)(bn + row) * NW + c * 8;
    }

    uint32_t offA[2][4];
#pragma unroll
    for (int mt = 0; mt < 2; ++mt)
#pragma unroll
        for (int ks = 0; ks < 4; ++ks) {
            int row = warp_m * 32 + mt * 16 + ((lane >> 3) & 1) * 8 + (lane & 7);
            int kc  = ks * 2 + (lane >> 4);
            offA[mt][ks] = row * ROWB + ((kc ^ (row & 7)) * 16);
        }
    uint32_t offB[4][4];
#pragma unroll
    for (int p = 0; p < 4; ++p)
#pragma unroll
        for (int ks = 0; ks < 4; ++ks) {
            int n  = warp_n * 64 + p * 16 + ((lane >> 4) & 1) * 8 + (lane & 7);
            int kc = ks * 2 + ((lane >> 3) & 1);
            offB[p][ks] = ASTG + n * ROWB + ((kc ^ (n & 7)) * 16);
        }

    float acc[2][8][4];
#pragma unroll
    for (int mt = 0; mt < 2; ++mt)
#pragma unroll
        for (int nt = 0; nt < 8; ++nt)
#pragma unroll
            for (int i = 0; i < 4; ++i) acc[mt][nt][i] = 0.0f;

#pragma unroll
    for (int s = 0; s < GSTAGES - 1; ++s) {
#pragma unroll
        for (int j = 0; j < 4; ++j) {
            cp_async16(dA[j] + s * STG_BYTES, sA[j] + s * BK);
            cp_async16(dB[j] + s * STG_BYTES, sB[j] + s * BK);
        }
        asm volatile("cp.async.commit_group;" ::: "memory");
    }

#pragma unroll 3
    for (int kt = 0; kt < KTILES; ++kt) {
        asm volatile("cp.async.wait_group 1;" ::: "memory");
        __syncthreads();

        if (kt + 2 < KTILES) {
            int s = (kt + 2) % 3;
#pragma unroll
            for (int j = 0; j < 4; ++j) {
                cp_async16(dA[j] + s * STG_BYTES, sA[j] + (size_t)(kt + 2) * BK);
                cp_async16(dB[j] + s * STG_BYTES, sB[j] + (size_t)(kt + 2) * BK);
            }
        }
        asm volatile("cp.async.commit_group;" ::: "memory");

        const uint32_t so = sbase + (kt % 3) * STG_BYTES;
#pragma unroll
        for (int ks = 0; ks < 4; ++ks) {
            uint32_t a[2][4], b[8][2];
#pragma unroll
            for (int mt = 0; mt < 2; ++mt)
                asm volatile("ldmatrix.sync.aligned.m8n8.x4.shared.b16 {%0,%1,%2,%3}, [%4];"
                             : "=r"(a[mt][0]), "=r"(a[mt][1]), "=r"(a[mt][2]), "=r"(a[mt][3])
                             : "r"(so + offA[mt][ks]));
#pragma unroll
            for (int p = 0; p < 4; ++p)
                asm volatile("ldmatrix.sync.aligned.m8n8.x4.shared.b16 {%0,%1,%2,%3}, [%4];"
                             : "=r"(b[2 * p][0]), "=r"(b[2 * p][1]),
                               "=r"(b[2 * p + 1][0]), "=r"(b[2 * p + 1][1])
                             : "r"(so + offB[p][ks]));
#pragma unroll
            for (int mt = 0; mt < 2; ++mt)
#pragma unroll
                for (int nt = 0; nt < 8; ++nt)
                    asm volatile(
                        "mma.sync.aligned.m16n8k16.row.col.f32.f16.f16.f32 "
                        "{%0,%1,%2,%3}, {%4,%5,%6,%7}, {%8,%9}, {%0,%1,%2,%3};"
                        : "+f"(acc[mt][nt][0]), "+f"(acc[mt][nt][1]),
                          "+f"(acc[mt][nt][2]), "+f"(acc[mt][nt][3])
                        : "r"(a[mt][0]), "r"(a[mt][1]), "r"(a[mt][2]), "r"(a[mt][3]),
                          "r"(b[nt][0]), "r"(b[nt][1]));
        }
    }

    const int g = lane >> 2, cq = lane & 3;
#pragma unroll
    for (int mt = 0; mt < 2; ++mt) {
        int r0 = bm + warp_m * 32 + mt * 16 + g;
#pragma unroll
        for (int nt = 0; nt < 8; ++nt) {
            int col = bn + warp_n * 64 + nt * 8 + 2 * cq;
            float2 bb = *(const float2*)(bias + col);
            float2 v0 = make_float2(acc[mt][nt][0] + bb.x, acc[mt][nt][1] + bb.y);
            float2 v1 = make_float2(acc[mt][nt][2] + bb.x, acc[mt][nt][3] + bb.y);
            *(float2*)(C + (size_t)r0 * DIM + col) = v0;
            *(float2*)(C + (size_t)(r0 + 8) * DIM + col) = v1;
        }
    }
}

// ---------------------------------------------------------------------------
extern "C" void kernel_launch(void* const* d_in, const int* in_sizes, int n_in,
                              void* d_out, int out_size)
{
    const float* hidden      = (const float*)d_in[0];
    const float* slot_w      = (const float*)d_in[1];
    const float* slot_b      = (const float*)d_in[2];
    const float* leaf_logits = (const float*)d_in[3];
    const float* node_params = (const float*)d_in[4];
    const float* out_w       = (const float*)d_in[5];
    const float* out_b       = (const float*)d_in[6];
    float* out = (float*)d_out;

    cudaFuncSetAttribute(gemm_mma_kernel,
                         cudaFuncAttributeMaxDynamicSharedMemorySize, GEMM_SMEM);

    slots_kernel<<<T_TOK, 128>>>(hidden, slot_w, slot_b);
    softmax_kernel<<<(NW * NLEAF + 255) / 256, 256>>>(leaf_logits);
    transpose_kernel<<<dim3(NW / 32, DIM / 32), 256>>>(out_w);
    roots_mma_kernel<<<dim3(NW / 64, T_TOK / 32), 256>>>(node_params);
    gemm_mma_kernel<<<dim3(DIM / BN, T_TOK / BM), 256, GEMM_SMEM>>>(out_b, out);
}

// round 12
// speedup vs baseline: 1.0072x; 1.0072x over previous
#include <cuda_runtime.h>
#include <cuda_fp16.h>
#include <cstdint>
#include <cstddef>

// Shape: B=2,S=2048 -> T=4096 tokens, D=1024, W=4096, SLOT=8, 8 leaves.
#define T_TOK   4096
#define DIM     1024
#define NW      4096
#define NSLOT   8
#define NLEAF   8

// Scratch (device globals; no allocation allowed)
__device__ __align__(1024) __half g_basis_h[(size_t)T_TOK * 16];      // slots,1,0...
__device__ __align__(1024) __half g_selB_h[(size_t)NLEAF * NW * 16];  // per-leaf sel rows
__device__ __align__(1024) __half g_roots_h[(size_t)T_TOK * NW];      // 32 MB
__device__ __align__(1024) __half g_outwT_h[(size_t)DIM * NW];        // 8 MB

// ---------------------------------------------------------------------------
__device__ __forceinline__ float tanh_mufu(float x) {
    float y;
    asm("tanh.approx.f32 %0, %1;" : "=f"(y) : "f"(x));
    return y;
}
__device__ __forceinline__ uint32_t smem_u32(const void* p) {
    uint32_t a;
    asm("{ .reg .u64 t; cvta.to.shared.u64 t, %1; cvt.u32.u64 %0, t; }" : "=r"(a) : "l"(p));
    return a;
}

// ---------------------------------------------------------------------------
// Kernel A: basis[t] = [tanh(hidden@slot_w+b) (8), 1.0, 0 x7] as fp16.
__global__ __launch_bounds__(128) void slots_kernel(
    const float* __restrict__ hidden,
    const float* __restrict__ slot_w,
    const float* __restrict__ slot_b)
{
    int t = blockIdx.x;
    const float* h = hidden + (size_t)t * DIM;
    float acc[NSLOT];
#pragma unroll
    for (int s = 0; s < NSLOT; ++s) acc[s] = 0.0f;

#pragma unroll
    for (int it = 0; it < 2; ++it) {
        int d = threadIdx.x * 4 + it * 512;
        float4 hv = *(const float4*)(h + d);
#pragma unroll
        for (int j = 0; j < 4; ++j) {
            float hx = (j == 0) ? hv.x : (j == 1) ? hv.y : (j == 2) ? hv.z : hv.w;
            const float* wr = slot_w + (size_t)(d + j) * NSLOT;
            float4 w0 = *(const float4*)(wr);
            float4 w1 = *(const float4*)(wr + 4);
            acc[0] = fmaf(hx, w0.x, acc[0]);
            acc[1] = fmaf(hx, w0.y, acc[1]);
            acc[2] = fmaf(hx, w0.z, acc[2]);
            acc[3] = fmaf(hx, w0.w, acc[3]);
            acc[4] = fmaf(hx, w1.x, acc[4]);
            acc[5] = fmaf(hx, w1.y, acc[5]);
            acc[6] = fmaf(hx, w1.z, acc[6]);
            acc[7] = fmaf(hx, w1.w, acc[7]);
        }
    }

#pragma unroll
    for (int s = 0; s < NSLOT; ++s) {
        float v = acc[s];
#pragma unroll
        for (int off = 16; off; off >>= 1)
            v += __shfl_xor_sync(0xffffffffu, v, off);
        acc[s] = v;
    }

    __shared__ float red[4][NSLOT];
    int lane = threadIdx.x & 31, warp = threadIdx.x >> 5;
    if (lane == 0) {
#pragma unroll
        for (int s = 0; s < NSLOT; ++s) red[warp][s] = acc[s];
    }
    __syncthreads();
    if (threadIdx.x < 16) {
        int s = threadIdx.x;
        __half o;
        if (s < NSLOT) {
            float v = red[0][s] + red[1][s] + red[2][s] + red[3][s] + slot_b[s];
            o = __float2half_rn(tanhf(v));
        } else if (s == 8) {
            o = __float2half_rn(1.0f);
        } else {
            o = __float2half_rn(0.0f);
        }
        g_basis_h[(size_t)t * 16 + s] = o;
    }
}

// ---------------------------------------------------------------------------
// Kernel B: softmax over 11 logits -> g_selB_h[l][w][16] fp16:
// [sel0..sel7, sel10-sel8, 0 x7]  (basis consts are -1,0,1)
__global__ __launch_bounds__(256) void softmax_kernel(const float* __restrict__ logits)
{
    int r = blockIdx.x * blockDim.x + threadIdx.x;   // w*8 + l
    if (r >= NW * NLEAF) return;
    int w = r >> 3, l = r & 7;
    const float* row = logits + (size_t)r * 11;
    float x[11];
    float m = -1e30f;
#pragma unroll
    for (int c = 0; c < 11; ++c) { x[c] = row[c]; m = fmaxf(m, x[c]); }
    float sum = 0.0f;
#pragma unroll
    for (int c = 0; c < 11; ++c) { x[c] = __expf(x[c] - m); sum += x[c]; }
    float inv = 1.0f / sum;

    __half2* dst = (__half2*)(g_selB_h + ((size_t)l * NW + w) * 16);
#pragma unroll
    for (int c = 0; c < 4; ++c)
        dst[c] = __floats2half2_rn(x[2 * c] * inv, x[2 * c + 1] * inv);
    dst[4] = __floats2half2_rn((x[10] - x[8]) * inv, 0.0f);
    __half2 z = __floats2half2_rn(0.0f, 0.0f);
    dst[5] = z; dst[6] = z; dst[7] = z;
}

// ---------------------------------------------------------------------------
// Kernel T: g_outwT_h[d][w] = half(out_w[w][d])
__global__ __launch_bounds__(256) void transpose_kernel(const float* __restrict__ Wm)
{
    __shared__ float t[32][33];
    int wt = blockIdx.x, dt = blockIdx.y;
    int tx = threadIdx.x & 31, ty = threadIdx.x >> 5;   // 32 x 8
#pragma unroll
    for (int i = 0; i < 4; ++i) {
        int w = wt * 32 + ty + i * 8;
        t[ty + i * 8][tx] = Wm[(size_t)w * DIM + dt * 32 + tx];
    }
    __syncthreads();
#pragma unroll
    for (int i = 0; i < 4; ++i) {
        int d = dt * 32 + ty + i * 8;
        g_outwT_h[(size_t)d * NW + wt * 32 + tx] = __float2half_rn(t[tx][ty + i * 8]);
    }
}

// ---------------------------------------------------------------------------
// Kernel C: leaf einsum via mma.sync + f32 tree reduce.
// CTA: 128 tokens x 64 w (grid 2048). 8 warps: warp_n = wid&3 (16 w each),
// tgrp = wid>>2; each warp processes 4 token tiles (m = tgrp + 2*it),
// reusing its 8 per-leaf B fragments held in registers.
__global__ __launch_bounds__(256) void roots_mma_kernel(const float* __restrict__ node_params)
{
    __shared__ __align__(16) char sAraw[128 * 32];         // 128 tok rows x 32B
    __shared__ __align__(16) char sBraw[8 * 64 * 32];      // [leaf][w] rows x 32B

    const int tid  = threadIdx.x;
    const int lane = tid & 31;
    const int wid  = tid >> 5;
    const int warp_n = wid & 3;          // w tile (16 each)
    const int tgrp   = wid >> 2;         // 0/1: token tiles {0,2,4,6} / {1,3,5,7}
    const int bt = blockIdx.y * 128;
    const int bw = blockIdx.x * 64;

    const uint32_t uA = smem_u32(sAraw);
    const uint32_t uB = smem_u32(sBraw);

    // ---- fill sA: 256 chunks of 16B (one per thread), swizzle c ^ ((row>>2)&1)
    {
        int row = tid >> 1, c = tid & 1;
        const uint4 v = *(const uint4*)(g_basis_h + (size_t)(bt + row) * 16 + c * 8);
        *(uint4*)(sAraw + row * 32 + ((c ^ ((row >> 2) & 1)) << 4)) = v;
    }
    // ---- fill sB: 1024 chunks, 4 per thread
#pragma unroll
    for (int j = 0; j < 4; ++j) {
        int id = tid + 256 * j;
        int l = id >> 7, w = (id >> 1) & 63, c = id & 1;
        const uint4 v = *(const uint4*)(g_selB_h + ((size_t)l * NW + bw + w) * 16 + c * 8);
        *(uint4*)(sBraw + l * 2048 + w * 32 + ((c ^ ((w >> 2) & 1)) << 4)) = v;
    }
    __syncthreads();

    // ---- B fragments for all 8 leaves, held in registers for the whole CTA tile
    uint32_t bfr[8][4];
    {
        int n  = warp_n * 16 + ((lane >> 4) & 1) * 8 + (lane & 7);
        int kc = (lane >> 3) & 1;
        uint32_t baddr = uB + n * 32 + ((kc ^ ((n >> 2) & 1)) << 4);
#pragma unroll
        for (int l = 0; l < 8; ++l)
            asm volatile("ldmatrix.sync.aligned.m8n8.x4.shared.b16 {%0,%1,%2,%3}, [%4];"
                         : "=r"(bfr[l][0]), "=r"(bfr[l][1]), "=r"(bfr[l][2]), "=r"(bfr[l][3])
                         : "r"(baddr + l * 2048));
    }

    // ---- tree params (3 FMA + 1 MUFU per node)
    float lw = __ldg(node_params + 0), rw = __ldg(node_params + 1);
    float pw = __ldg(node_params + 2), dw = __ldg(node_params + 3);
    float nb = __ldg(node_params + 4);
    float la = lw + dw, ra = rw - dw;

    const int g = lane >> 2, cq = lane & 3;

#pragma unroll
    for (int it = 0; it < 4; ++it) {
        const int m = tgrp + 2 * it;         // token tile 0..7

        // A fragment (m16 x k16) for this token tile
        uint32_t a[4];
        {
            int row = m * 16 + ((lane >> 3) & 1) * 8 + (lane & 7);
            int kc  = lane >> 4;
            uint32_t addr = uA + row * 32 + ((kc ^ ((row >> 2) & 1)) << 4);
            asm volatile("ldmatrix.sync.aligned.m8n8.x4.shared.b16 {%0,%1,%2,%3}, [%4];"
                         : "=r"(a[0]), "=r"(a[1]), "=r"(a[2]), "=r"(a[3]) : "r"(addr));
        }

        float acc[2][8][4];
#pragma unroll
        for (int nt = 0; nt < 2; ++nt)
#pragma unroll
            for (int l = 0; l < 8; ++l)
#pragma unroll
                for (int i = 0; i < 4; ++i) acc[nt][l][i] = 0.0f;

#pragma unroll
        for (int l = 0; l < 8; ++l) {
            asm volatile(
                "mma.sync.aligned.m16n8k16.row.col.f32.f16.f16.f32 "
                "{%0,%1,%2,%3}, {%4,%5,%6,%7}, {%8,%9}, {%0,%1,%2,%3};"
                : "+f"(acc[0][l][0]), "+f"(acc[0][l][1]), "+f"(acc[0][l][2]), "+f"(acc[0][l][3])
                : "r"(a[0]), "r"(a[1]), "r"(a[2]), "r"(a[3]),
                  "r"(bfr[l][0]), "r"(bfr[l][1]));
            asm volatile(
                "mma.sync.aligned.m16n8k16.row.col.f32.f16.f16.f32 "
                "{%0,%1,%2,%3}, {%4,%5,%6,%7}, {%8,%9}, {%0,%1,%2,%3};"
                : "+f"(acc[1][l][0]), "+f"(acc[1][l][1]), "+f"(acc[1][l][2]), "+f"(acc[1][l][3])
                : "r"(a[0]), "r"(a[1]), "r"(a[2]), "r"(a[3]),
                  "r"(bfr[l][2]), "r"(bfr[l][3]));
        }

        // tree reduce per (token,w) position
#pragma unroll
        for (int nt = 0; nt < 2; ++nt) {
            float roots[4];
#pragma unroll
            for (int ci = 0; ci < 4; ++ci) {
                float x[8];
#pragma unroll
                for (int l = 0; l < 8; ++l) x[l] = acc[nt][l][ci];
#pragma unroll
                for (int d = 0; d < 3; ++d) {
                    int n = NLEAF >> (d + 1);
#pragma unroll
                    for (int i = 0; i < 4; ++i) {
                        if (i < n) {
                            float L = x[2 * i], R = x[2 * i + 1];
                            // z = la*L + ra*R + pw*L*R + nb = L*(pw*R+la) + (ra*R+nb)
                            x[i] = tanh_mufu(fmaf(L, fmaf(pw, R, la), fmaf(ra, R, nb)));
                        }
                    }
                }
                roots[ci] = x[0];
            }
            int col = bw + warp_n * 16 + nt * 8 + 2 * cq;
            int r0  = bt + m * 16 + g;
            *(__half2*)(g_roots_h + (size_t)r0 * NW + col)       = __floats2half2_rn(roots[0], roots[1]);
            *(__half2*)(g_roots_h + (size_t)(r0 + 8) * NW + col) = __floats2half2_rn(roots[2], roots[3]);
        }
    }
}

// ---------------------------------------------------------------------------
// Kernel D: fp16 mma.sync GEMM, BK=64 (3 stages x 32KB = 96KB smem). (R9 version)
#define BM 128
#define BN 128
#define BK 64
#define KTILES (NW / BK)                  // 64
#define ROWB (BK * 2)                     // 128 bytes/row
#define ASTG (BM * ROWB)                  // 16384
#define BSTG (BN * ROWB)                  // 16384
#define STG_BYTES (ASTG + BSTG)           // 32768
#define GSTAGES 3
#define GEMM_SMEM (GSTAGES * STG_BYTES)   // 98304

__device__ __forceinline__ void cp_async16(uint32_t dst, const void* src) {
    asm volatile("cp.async.cg.shared.global [%0], [%1], 16;" :: "r"(dst), "l"(src));
}

__global__ __launch_bounds__(256, 2) void gemm_mma_kernel(
    const float* __restrict__ bias, float* __restrict__ C)
{
    extern __shared__ char smem[];
    const uint32_t sbase = smem_u32(smem);

    const int tid  = threadIdx.x;
    const int lane = tid & 31;
    const int wid  = tid >> 5;
    const int warp_m = wid >> 1;
    const int warp_n = wid & 1;
    const int bm = blockIdx.y * BM;
    const int bn = blockIdx.x * BN;

    const __half* Ah = g_roots_h;
    const __half* Bh = g_outwT_h;

    uint32_t dA[4], dB[4];
    const __half* sA[4];
    const __half* sB[4];
#pragma unroll
    for (int j = 0; j < 4; ++j) {
        int id  = tid + 256 * j;          // 0..1023
        int row = id >> 3, c = id & 7;
        int sw  = c ^ (row & 7);
        dA[j] = sbase + row * ROWB + sw * 16;
        dB[j] = sbase + ASTG + row * ROWB + sw * 16;
        sA[j] = Ah + (size_t)(bm + row) * NW + c * 8;
        sB[j] = Bh + (size_t)(bn + row) * NW + c * 8;
    }

    uint32_t offA[2][4];
#pragma unroll
    for (int mt = 0; mt < 2; ++mt)
#pragma unroll
        for (int ks = 0; ks < 4; ++ks) {
            int row = warp_m * 32 + mt * 16 + ((lane >> 3) & 1) * 8 + (lane & 7);
            int kc  = ks * 2 + (lane >> 4);
            offA[mt][ks] = row * ROWB + ((kc ^ (row & 7)) * 16);
        }
    uint32_t offB[4][4];
#pragma unroll
    for (int p = 0; p < 4; ++p)
#pragma unroll
        for (int ks = 0; ks < 4; ++ks) {
            int n  = warp_n * 64 + p * 16 + ((lane >> 4) & 1) * 8 + (lane & 7);
            int kc = ks * 2 + ((lane >> 3) & 1);
            offB[p][ks] = ASTG + n * ROWB + ((kc ^ (n & 7)) * 16);
        }

    float acc[2][8][4];
#pragma unroll
    for (int mt = 0; mt < 2; ++mt)
#pragma unroll
        for (int nt = 0; nt < 8; ++nt)
#pragma unroll
            for (int i = 0; i < 4; ++i) acc[mt][nt][i] = 0.0f;

#pragma unroll
    for (int s = 0; s < GSTAGES - 1; ++s) {
#pragma unroll
        for (int j = 0; j < 4; ++j) {
            cp_async16(dA[j] + s * STG_BYTES, sA[j] + s * BK);
            cp_async16(dB[j] + s * STG_BYTES, sB[j] + s * BK);
        }
        asm volatile("cp.async.commit_group;" ::: "memory");
    }

    for (int kt = 0; kt < KTILES; ++kt) {
        asm volatile("cp.async.wait_group 1;" ::: "memory");
        __syncthreads();

        if (kt + 2 < KTILES) {
            int s = (kt + 2) % 3;
#pragma unroll
            for (int j = 0; j < 4; ++j) {
                cp_async16(dA[j] + s * STG_BYTES, sA[j] + (size_t)(kt + 2) * BK);
                cp_async16(dB[j] + s * STG_BYTES, sB[j] + (size_t)(kt + 2) * BK);
            }
        }
        asm volatile("cp.async.commit_group;" ::: "memory");

        const uint32_t so = sbase + (kt % 3) * STG_BYTES;
#pragma unroll
        for (int ks = 0; ks < 4; ++ks) {
            uint32_t a[2][4], b[8][2];
#pragma unroll
            for (int mt = 0; mt < 2; ++mt)
                asm volatile("ldmatrix.sync.aligned.m8n8.x4.shared.b16 {%0,%1,%2,%3}, [%4];"
                             : "=r"(a[mt][0]), "=r"(a[mt][1]), "=r"(a[mt][2]), "=r"(a[mt][3])
                             : "r"(so + offA[mt][ks]));
#pragma unroll
            for (int p = 0; p < 4; ++p)
                asm volatile("ldmatrix.sync.aligned.m8n8.x4.shared.b16 {%0,%1,%2,%3}, [%4];"
                             : "=r"(b[2 * p][0]), "=r"(b[2 * p][1]),
                               "=r"(b[2 * p + 1][0]), "=r"(b[2 * p + 1][1])
                             : "r"(so + offB[p][ks]));
#pragma unroll
            for (int mt = 0; mt < 2; ++mt)
#pragma unroll
                for (int nt = 0; nt < 8; ++nt)
                    asm volatile(
                        "mma.sync.aligned.m16n8k16.row.col.f32.f16.f16.f32 "
                        "{%0,%1,%2,%3}, {%4,%5,%6,%7}, {%8,%9}, {%0,%1,%2,%3};"
                        : "+f"(acc[mt][nt][0]), "+f"(acc[mt][nt][1]),
                          "+f"(acc[mt][nt][2]), "+f"(acc[mt][nt][3])
                        : "r"(a[mt][0]), "r"(a[mt][1]), "r"(a[mt][2]), "r"(a[mt][3]),
                          "r"(b[nt][0]), "r"(b[nt][1]));
        }
    }

    const int g = lane >> 2, cq = lane & 3;
#pragma unroll
    for (int mt = 0; mt < 2; ++mt) {
        int r0 = bm + warp_m * 32 + mt * 16 + g;
#pragma unroll
        for (int nt = 0; nt < 8; ++nt) {
            int col = bn + warp_n * 64 + nt * 8 + 2 * cq;
            float2 bb = *(const float2*)(bias + col);
            float2 v0 = make_float2(acc[mt][nt][0] + bb.x, acc[mt][nt][1] + bb.y);
            float2 v1 = make_float2(acc[mt][nt][2] + bb.x, acc[mt][nt][3] + bb.y);
            *(float2*)(C + (size_t)r0 * DIM + col) = v0;
            *(float2*)(C + (size_t)(r0 + 8) * DIM + col) = v1;
        }
    }
}

// ---------------------------------------------------------------------------
extern "C" void kernel_launch(void* const* d_in, const int* in_sizes, int n_in,
                              void* d_out, int out_size)
{
    const float* hidden      = (const float*)d_in[0];
    const float* slot_w      = (const float*)d_in[1];
    const float* slot_b      = (const float*)d_in[2];
    const float* leaf_logits = (const float*)d_in[3];
    const float* node_params = (const float*)d_in[4];
    const float* out_w       = (const float*)d_in[5];
    const float* out_b       = (const float*)d_in[6];
    float* out = (float*)d_out;

    cudaFuncSetAttribute(gemm_mma_kernel,
                         cudaFuncAttributeMaxDynamicSharedMemorySize, GEMM_SMEM);

    slots_kernel<<<T_TOK, 128>>>(hidden, slot_w, slot_b);
    softmax_kernel<<<(NW * NLEAF + 255) / 256, 256>>>(leaf_logits);
    transpose_kernel<<<dim3(NW / 32, DIM / 32), 256>>>(out_w);
    roots_mma_kernel<<<dim3(NW / 64, T_TOK / 128), 256>>>(node_params);
    gemm_mma_kernel<<<dim3(DIM / BN, T_TOK / BM), 256, GEMM_SMEM>>>(out_b, out);
}

// round 14
// speedup vs baseline: 1.0794x; 1.0717x over previous
#include <cuda_runtime.h>
#include <cuda_fp16.h>
#include <cstdint>
#include <cstddef>

// Shape: B=2,S=2048 -> T=4096 tokens, D=1024, W=4096, SLOT=8, 8 leaves.
#define T_TOK   4096
#define DIM     1024
#define NW      4096
#define NSLOT   8
#define NLEAF   8

// Scratch (device globals; no allocation allowed)
__device__ __align__(1024) __half g_basis_h[(size_t)T_TOK * 16];      // slots,1,0...
__device__ __align__(1024) __half g_selB_h[(size_t)NLEAF * NW * 16];  // per-leaf sel rows
__device__ __align__(1024) __half g_roots_h[(size_t)T_TOK * NW];      // 32 MB
__device__ __align__(1024) __half g_outwT_h[(size_t)DIM * NW];        // 8 MB

// ---------------------------------------------------------------------------
__device__ __forceinline__ float tanh_mufu(float x) {
    float y;
    asm("tanh.approx.f32 %0, %1;" : "=f"(y) : "f"(x));
    return y;
}
__device__ __forceinline__ uint32_t smem_u32(const void* p) {
    uint32_t a;
    asm("{ .reg .u64 t; cvta.to.shared.u64 t, %1; cvt.u32.u64 %0, t; }" : "=r"(a) : "l"(p));
    return a;
}

// ---------------------------------------------------------------------------
// Fused prep kernel: blocks [0,2048) slots (2 tokens/block),
// [2048,2176) softmax, [2176,6272) transpose.
#define PREP_SLOTS_BLKS 2048
#define PREP_SMAX_BLKS  128
#define PREP_TRANS_BLKS 4096
#define PREP_BLKS (PREP_SLOTS_BLKS + PREP_SMAX_BLKS + PREP_TRANS_BLKS)

__global__ __launch_bounds__(256) void prep_kernel(
    const float* __restrict__ hidden,
    const float* __restrict__ slot_w,
    const float* __restrict__ slot_b,
    const float* __restrict__ logits,
    const float* __restrict__ Wm)
{
    __shared__ float red[2][4][NSLOT];
    __shared__ float tsm[32][33];

    const int b = blockIdx.x;
    if (b < PREP_SLOTS_BLKS) {
        // ---- slots: 2 tokens per block
        int half = threadIdx.x >> 7;      // 0/1
        int wtid = threadIdx.x & 127;
        int t = b * 2 + half;
        const float* h = hidden + (size_t)t * DIM;
        float acc[NSLOT];
#pragma unroll
        for (int s = 0; s < NSLOT; ++s) acc[s] = 0.0f;

#pragma unroll
        for (int it = 0; it < 2; ++it) {
            int d = wtid * 4 + it * 512;
            float4 hv = *(const float4*)(h + d);
#pragma unroll
            for (int j = 0; j < 4; ++j) {
                float hx = (j == 0) ? hv.x : (j == 1) ? hv.y : (j == 2) ? hv.z : hv.w;
                const float* wr = slot_w + (size_t)(d + j) * NSLOT;
                float4 w0 = *(const float4*)(wr);
                float4 w1 = *(const float4*)(wr + 4);
                acc[0] = fmaf(hx, w0.x, acc[0]);
                acc[1] = fmaf(hx, w0.y, acc[1]);
                acc[2] = fmaf(hx, w0.z, acc[2]);
                acc[3] = fmaf(hx, w0.w, acc[3]);
                acc[4] = fmaf(hx, w1.x, acc[4]);
                acc[5] = fmaf(hx, w1.y, acc[5]);
                acc[6] = fmaf(hx, w1.z, acc[6]);
                acc[7] = fmaf(hx, w1.w, acc[7]);
            }
        }

#pragma unroll
        for (int s = 0; s < NSLOT; ++s) {
            float v = acc[s];
#pragma unroll
            for (int off = 16; off; off >>= 1)
                v += __shfl_xor_sync(0xffffffffu, v, off);
            acc[s] = v;
        }

        int lane = wtid & 31, warp = wtid >> 5;
        if (lane == 0) {
#pragma unroll
            for (int s = 0; s < NSLOT; ++s) red[half][warp][s] = acc[s];
        }
        __syncthreads();
        if (wtid < 16) {
            int s = wtid;
            __half o;
            if (s < NSLOT) {
                float v = red[half][0][s] + red[half][1][s] +
                          red[half][2][s] + red[half][3][s] + slot_b[s];
                o = __float2half_rn(tanhf(v));
            } else if (s == 8) {
                o = __float2half_rn(1.0f);
            } else {
                o = __float2half_rn(0.0f);
            }
            g_basis_h[(size_t)t * 16 + s] = o;
        }
    } else if (b < PREP_SLOTS_BLKS + PREP_SMAX_BLKS) {
        // ---- softmax (one row per thread)
        int r = (b - PREP_SLOTS_BLKS) * 256 + threadIdx.x;   // < 32768
        int w = r >> 3, l = r & 7;
        const float* row = logits + (size_t)r * 11;
        float x[11];
        float m = -1e30f;
#pragma unroll
        for (int c = 0; c < 11; ++c) { x[c] = row[c]; m = fmaxf(m, x[c]); }
        float sum = 0.0f;
#pragma unroll
        for (int c = 0; c < 11; ++c) { x[c] = __expf(x[c] - m); sum += x[c]; }
        float inv = 1.0f / sum;

        __half2* dst = (__half2*)(g_selB_h + ((size_t)l * NW + w) * 16);
#pragma unroll
        for (int c = 0; c < 4; ++c)
            dst[c] = __floats2half2_rn(x[2 * c] * inv, x[2 * c + 1] * inv);
        dst[4] = __floats2half2_rn((x[10] - x[8]) * inv, 0.0f);
        __half2 z = __floats2half2_rn(0.0f, 0.0f);
        dst[5] = z; dst[6] = z; dst[7] = z;
    } else {
        // ---- transpose tile
        int tb = b - (PREP_SLOTS_BLKS + PREP_SMAX_BLKS);
        int wt = tb >> 5;    // 0..127
        int dt = tb & 31;    // 0..31
        int tx = threadIdx.x & 31, ty = threadIdx.x >> 5;   // 32 x 8
#pragma unroll
        for (int i = 0; i < 4; ++i) {
            int w = wt * 32 + ty + i * 8;
            tsm[ty + i * 8][tx] = Wm[(size_t)w * DIM + dt * 32 + tx];
        }
        __syncthreads();
#pragma unroll
        for (int i = 0; i < 4; ++i) {
            int d = dt * 32 + ty + i * 8;
            g_outwT_h[(size_t)d * NW + wt * 32 + tx] = __float2half_rn(tsm[tx][ty + i * 8]);
        }
    }
}

// ---------------------------------------------------------------------------
// Kernel C: leaf einsum via mma.sync + f32 tree reduce.
// CTA: 128 tokens x 64 w (grid 64x32). 8 warps: warp_n = wid&3 (16 w),
// tgrp = wid>>2; 4 token tiles per warp. nt processed one at a time to
// keep only 32 acc regs live (target 3 CTAs/SM).
__global__ __launch_bounds__(256) void roots_mma_kernel(const float* __restrict__ node_params)
{
    __shared__ __align__(16) char sAraw[128 * 32];         // 128 tok rows x 32B
    __shared__ __align__(16) char sBraw[8 * 64 * 32];      // [leaf][w] rows x 32B

    const int tid  = threadIdx.x;
    const int lane = tid & 31;
    const int wid  = tid >> 5;
    const int warp_n = wid & 3;          // w tile (16 each)
    const int tgrp   = wid >> 2;         // 0/1
    const int bt = blockIdx.y * 128;
    const int bw = blockIdx.x * 64;

    const uint32_t uA = smem_u32(sAraw);
    const uint32_t uB = smem_u32(sBraw);

    // ---- fill sA: 256 chunks of 16B (one per thread), swizzle c ^ ((row>>2)&1)
    {
        int row = tid >> 1, c = tid & 1;
        const uint4 v = *(const uint4*)(g_basis_h + (size_t)(bt + row) * 16 + c * 8);
        *(uint4*)(sAraw + row * 32 + ((c ^ ((row >> 2) & 1)) << 4)) = v;
    }
    // ---- fill sB: 1024 chunks, 4 per thread
#pragma unroll
    for (int j = 0; j < 4; ++j) {
        int id = tid + 256 * j;
        int l = id >> 7, w = (id >> 1) & 63, c = id & 1;
        const uint4 v = *(const uint4*)(g_selB_h + ((size_t)l * NW + bw + w) * 16 + c * 8);
        *(uint4*)(sBraw + l * 2048 + w * 32 + ((c ^ ((w >> 2) & 1)) << 4)) = v;
    }
    __syncthreads();

    // ---- B fragments for all 8 leaves (kept in regs for whole CTA tile)
    uint32_t bfr[8][4];
    {
        int n  = warp_n * 16 + ((lane >> 4) & 1) * 8 + (lane & 7);
        int kc = (lane >> 3) & 1;
        uint32_t baddr = uB + n * 32 + ((kc ^ ((n >> 2) & 1)) << 4);
#pragma unroll
        for (int l = 0; l < 8; ++l)
            asm volatile("ldmatrix.sync.aligned.m8n8.x4.shared.b16 {%0,%1,%2,%3}, [%4];"
                         : "=r"(bfr[l][0]), "=r"(bfr[l][1]), "=r"(bfr[l][2]), "=r"(bfr[l][3])
                         : "r"(baddr + l * 2048));
    }

    float lw = __ldg(node_params + 0), rw = __ldg(node_params + 1);
    float pw = __ldg(node_params + 2), dw = __ldg(node_params + 3);
    float nb = __ldg(node_params + 4);
    float la = lw + dw, ra = rw - dw;

    const int g = lane >> 2, cq = lane & 3;

#pragma unroll
    for (int it = 0; it < 4; ++it) {
        const int m = tgrp + 2 * it;         // token tile 0..7

        uint32_t a[4];
        {
            int row = m * 16 + ((lane >> 3) & 1) * 8 + (lane & 7);
            int kc  = lane >> 4;
            uint32_t addr = uA + row * 32 + ((kc ^ ((row >> 2) & 1)) << 4);
            asm volatile("ldmatrix.sync.aligned.m8n8.x4.shared.b16 {%0,%1,%2,%3}, [%4];"
                         : "=r"(a[0]), "=r"(a[1]), "=r"(a[2]), "=r"(a[3]) : "r"(addr));
        }

#pragma unroll
        for (int nt = 0; nt < 2; ++nt) {
            float acc[8][4];
#pragma unroll
            for (int l = 0; l < 8; ++l)
#pragma unroll
                for (int i = 0; i < 4; ++i) acc[l][i] = 0.0f;

#pragma unroll
            for (int l = 0; l < 8; ++l)
                asm volatile(
                    "mma.sync.aligned.m16n8k16.row.col.f32.f16.f16.f32 "
                    "{%0,%1,%2,%3}, {%4,%5,%6,%7}, {%8,%9}, {%0,%1,%2,%3};"
                    : "+f"(acc[l][0]), "+f"(acc[l][1]), "+f"(acc[l][2]), "+f"(acc[l][3])
                    : "r"(a[0]), "r"(a[1]), "r"(a[2]), "r"(a[3]),
                      "r"(bfr[l][2 * nt]), "r"(bfr[l][2 * nt + 1]));

            float roots[4];
#pragma unroll
            for (int ci = 0; ci < 4; ++ci) {
                float x[8];
#pragma unroll
                for (int l = 0; l < 8; ++l) x[l] = acc[l][ci];
#pragma unroll
                for (int d = 0; d < 3; ++d) {
                    int n = NLEAF >> (d + 1);
#pragma unroll
                    for (int i = 0; i < 4; ++i) {
                        if (i < n) {
                            float L = x[2 * i], R = x[2 * i + 1];
                            x[i] = tanh_mufu(fmaf(L, fmaf(pw, R, la), fmaf(ra, R, nb)));
                        }
                    }
                }
                roots[ci] = x[0];
            }
            int col = bw + warp_n * 16 + nt * 8 + 2 * cq;
            int r0  = bt + m * 16 + g;
            *(__half2*)(g_roots_h + (size_t)r0 * NW + col)       = __floats2half2_rn(roots[0], roots[1]);
            *(__half2*)(g_roots_h + (size_t)(r0 + 8) * NW + col) = __floats2half2_rn(roots[2], roots[3]);
        }
    }
}

// ---------------------------------------------------------------------------
// Kernel D: fp16 mma.sync GEMM. 128x128x64 CTA tile, 4 warps of 64x64,
// 3-stage cp.async (96KB). Swizzle: chunk ^ (row&7); all row deltas are
// multiples of 8 so swizzle terms are loop-invariant.
#define BM 128
#define BN 128
#define BK 64
#define KTILES (NW / BK)                  // 64
#define ROWB (BK * 2)                     // 128 bytes/row
#define ASTG (BM * ROWB)                  // 16384
#define BSTG (BN * ROWB)                  // 16384
#define STG_BYTES (ASTG + BSTG)           // 32768
#define GSTAGES 3
#define GEMM_SMEM (GSTAGES * STG_BYTES)   // 98304

__device__ __forceinline__ void cp_async16(uint32_t dst, const void* src) {
    asm volatile("cp.async.cg.shared.global [%0], [%1], 16;" :: "r"(dst), "l"(src));
}

__global__ __launch_bounds__(128, 2) void gemm_mma_kernel(
    const float* __restrict__ bias, float* __restrict__ C)
{
    extern __shared__ char smem[];
    const uint32_t sbase = smem_u32(smem);

    const int tid  = threadIdx.x;
    const int lane = tid & 31;
    const int wid  = tid >> 5;
    const int warp_m = wid & 1;          // 64 rows each
    const int warp_n = wid >> 1;         // 64 cols each
    const int bm = blockIdx.y * BM;
    const int bn = blockIdx.x * BN;

    const __half* Ah = g_roots_h;
    const __half* Bh = g_outwT_h;

    // ---- cp.async bases: thread covers rows row0 + 16j (j=0..7), fixed chunk c
    const int row0 = tid >> 3, c0 = tid & 7;
    const int sw0  = c0 ^ (row0 & 7);
    const uint32_t dAbase = sbase + row0 * ROWB + sw0 * 16;
    const uint32_t dBbase = dAbase + ASTG;
    const __half* sAbase = Ah + (size_t)(bm + row0) * NW + c0 * 8;
    const __half* sBbase = Bh + (size_t)(bn + row0) * NW + c0 * 8;

    // ---- ldmatrix base offsets (swizzle parts loop-invariant: row&7 = lane&7)
    const int r7 = lane & 7;
    const uint32_t aRowBase = (uint32_t)((warp_m * 64 + ((lane >> 3) & 1) * 8 + r7) * ROWB);
    const uint32_t bRowBase = (uint32_t)(ASTG + (warp_n * 64 + ((lane >> 4) & 1) * 8 + r7) * ROWB);
    uint32_t kcA[4], kcB[4];
#pragma unroll
    for (int ks = 0; ks < 4; ++ks) {
        kcA[ks] = (uint32_t)(((ks * 2 + (lane >> 4)) ^ r7) << 4);
        kcB[ks] = (uint32_t)(((ks * 2 + ((lane >> 3) & 1)) ^ r7) << 4);
    }

    float acc[4][8][4];
#pragma unroll
    for (int mt = 0; mt < 4; ++mt)
#pragma unroll
        for (int nt = 0; nt < 8; ++nt)
#pragma unroll
            for (int i = 0; i < 4; ++i) acc[mt][nt][i] = 0.0f;

    // ---- prologue: stages 0..1
#pragma unroll
    for (int s = 0; s < GSTAGES - 1; ++s) {
#pragma unroll
        for (int j = 0; j < 8; ++j) {
            cp_async16(dAbase + s * STG_BYTES + j * 16 * ROWB,
                       sAbase + (size_t)j * 16 * NW + s * BK);
            cp_async16(dBbase + s * STG_BYTES + j * 16 * ROWB,
                       sBbase + (size_t)j * 16 * NW + s * BK);
        }
        asm volatile("cp.async.commit_group;" ::: "memory");
    }

    for (int kt = 0; kt < KTILES; ++kt) {
        asm volatile("cp.async.wait_group 1;" ::: "memory");
        __syncthreads();

        if (kt + 2 < KTILES) {
            int s = (kt + 2) % 3;
#pragma unroll
            for (int j = 0; j < 8; ++j) {
                cp_async16(dAbase + s * STG_BYTES + j * 16 * ROWB,
                           sAbase + (size_t)j * 16 * NW + (size_t)(kt + 2) * BK);
                cp_async16(dBbase + s * STG_BYTES + j * 16 * ROWB,
                           sBbase + (size_t)j * 16 * NW + (size_t)(kt + 2) * BK);
            }
        }
        asm volatile("cp.async.commit_group;" ::: "memory");

        const uint32_t so = sbase + (kt % 3) * STG_BYTES;
#pragma unroll
        for (int ks = 0; ks < 4; ++ks) {
            uint32_t a[4][4], b[8][2];
#pragma unroll
            for (int mt = 0; mt < 4; ++mt)
                asm volatile("ldmatrix.sync.aligned.m8n8.x4.shared.b16 {%0,%1,%2,%3}, [%4];"
                             : "=r"(a[mt][0]), "=r"(a[mt][1]), "=r"(a[mt][2]), "=r"(a[mt][3])
                             : "r"(so + aRowBase + mt * 16 * ROWB + kcA[ks]));
#pragma unroll
            for (int p = 0; p < 4; ++p)
                asm volatile("ldmatrix.sync.aligned.m8n8.x4.shared.b16 {%0,%1,%2,%3}, [%4];"
                             : "=r"(b[2 * p][0]), "=r"(b[2 * p][1]),
                               "=r"(b[2 * p + 1][0]), "=r"(b[2 * p + 1][1])
                             : "r"(so + bRowBase + p * 16 * ROWB + kcB[ks]));
#pragma unroll
            for (int mt = 0; mt < 4; ++mt)
#pragma unroll
                for (int nt = 0; nt < 8; ++nt)
                    asm volatile(
                        "mma.sync.aligned.m16n8k16.row.col.f32.f16.f16.f32 "
                        "{%0,%1,%2,%3}, {%4,%5,%6,%7}, {%8,%9}, {%0,%1,%2,%3};"
                        : "+f"(acc[mt][nt][0]), "+f"(acc[mt][nt][1]),
                          "+f"(acc[mt][nt][2]), "+f"(acc[mt][nt][3])
                        : "r"(a[mt][0]), "r"(a[mt][1]), "r"(a[mt][2]), "r"(a[mt][3]),
                          "r"(b[nt][0]), "r"(b[nt][1]));
        }
    }

    const int g = lane >> 2, cq = lane & 3;
#pragma unroll
    for (int mt = 0; mt < 4; ++mt) {
        int r0 = bm + warp_m * 64 + mt * 16 + g;
#pragma unroll
        for (int nt = 0; nt < 8; ++nt) {
            int col = bn + warp_n * 64 + nt * 8 + 2 * cq;
            float2 bb = *(const float2*)(bias + col);
            float2 v0 = make_float2(acc[mt][nt][0] + bb.x, acc[mt][nt][1] + bb.y);
            float2 v1 = make_float2(acc[mt][nt][2] + bb.x, acc[mt][nt][3] + bb.y);
            *(float2*)(C + (size_t)r0 * DIM + col) = v0;
            *(float2*)(C + (size_t)(r0 + 8) * DIM + col) = v1;
        }
    }
}

// ---------------------------------------------------------------------------
extern "C" void kernel_launch(void* const* d_in, const int* in_sizes, int n_in,
                              void* d_out, int out_size)
{
    const float* hidden      = (const float*)d_in[0];
    const float* slot_w      = (const float*)d_in[1];
    const float* slot_b      = (const float*)d_in[2];
    const float* leaf_logits = (const float*)d_in[3];
    const float* node_params = (const float*)d_in[4];
    const float* out_w       = (const float*)d_in[5];
    const float* out_b       = (const float*)d_in[6];
    float* out = (float*)d_out;

    cudaFuncSetAttribute(gemm_mma_kernel,
                         cudaFuncAttributeMaxDynamicSharedMemorySize, GEMM_SMEM);

    prep_kernel<<<PREP_BLKS, 256>>>(hidden, slot_w, slot_b, leaf_logits, out_w);
    roots_mma_kernel<<<dim3(NW / 64, T_TOK / 128), 256>>>(node_params);
    gemm_mma_kernel<<<dim3(DIM / BN, T_TOK / BM), 128, GEMM_SMEM>>>(out_b, out);
}

// round 15
// speedup vs baseline: 1.2506x; 1.1587x over previous
#include <cuda_runtime.h>
#include <cuda_fp16.h>
#include <cstdint>
#include <cstddef>

// Shape: B=2,S=2048 -> T=4096 tokens, D=1024, W=4096, SLOT=8, 8 leaves.
#define T_TOK   4096
#define DIM     1024
#define NW      4096
#define NSLOT   8
#define NLEAF   8

// Scratch (device globals; no allocation allowed)
__device__ __align__(1024) __half g_basis_h[(size_t)T_TOK * 16];      // slots,1,0...
__device__ __align__(1024) __half g_selB_h[(size_t)NLEAF * NW * 16];  // per-leaf sel rows
__device__ __align__(1024) __half g_roots_h[(size_t)T_TOK * NW];      // 32 MB
__device__ __align__(1024) __half g_outwT_h[(size_t)DIM * NW];        // 8 MB

// ---------------------------------------------------------------------------
__device__ __forceinline__ float tanh_mufu(float x) {
    float y;
    asm("tanh.approx.f32 %0, %1;" : "=f"(y) : "f"(x));
    return y;
}
__device__ __forceinline__ uint32_t smem_u32(const void* p) {
    uint32_t a;
    asm("{ .reg .u64 t; cvta.to.shared.u64 t, %1; cvt.u32.u64 %0, t; }" : "=r"(a) : "l"(p));
    return a;
}

// ---------------------------------------------------------------------------
// Fused prep kernel: blocks [0,1024) slots (4 tokens/block, smem-staged slot_w),
// [1024,1152) softmax, [1152,5248) transpose.
#define PREP_SLOTS_BLKS 1024
#define PREP_SMAX_BLKS  128
#define PREP_TRANS_BLKS 4096
#define PREP_BLKS (PREP_SLOTS_BLKS + PREP_SMAX_BLKS + PREP_TRANS_BLKS)

__global__ __launch_bounds__(256) void prep_kernel(
    const float* __restrict__ hidden,
    const float* __restrict__ slot_w,
    const float* __restrict__ slot_b,
    const float* __restrict__ logits,
    const float* __restrict__ Wm)
{
    __shared__ float swT[NSLOT][DIM];     // slot_w transposed (32 KB)
    __shared__ float red[4][2][NSLOT];
    __shared__ float tsm[32][33];

    const int b = blockIdx.x;
    if (b < PREP_SLOTS_BLKS) {
        // ---- stage slot_w transposed: coalesced read, conflict-free-ish writes
#pragma unroll
        for (int k = 0; k < 4; ++k) {
            int r = threadIdx.x + k * 256;             // slot_w row (d index)
            float4 w0 = *(const float4*)(slot_w + (size_t)r * NSLOT);
            float4 w1 = *(const float4*)(slot_w + (size_t)r * NSLOT + 4);
            swT[0][r] = w0.x; swT[1][r] = w0.y; swT[2][r] = w0.z; swT[3][r] = w0.w;
            swT[4][r] = w1.x; swT[5][r] = w1.y; swT[6][r] = w1.z; swT[7][r] = w1.w;
        }
        __syncthreads();

        // ---- 4 tokens per block, 64 threads each
        int tok  = threadIdx.x >> 6;
        int wtid = threadIdx.x & 63;
        int t = b * 4 + tok;
        const float* h = hidden + (size_t)t * DIM;

        float acc[NSLOT];
#pragma unroll
        for (int s = 0; s < NSLOT; ++s) acc[s] = 0.0f;

#pragma unroll
        for (int it = 0; it < 4; ++it) {
            int d = wtid * 4 + it * 256;
            float4 hv = *(const float4*)(h + d);
#pragma unroll
            for (int s = 0; s < NSLOT; ++s) {
                float4 w = *(const float4*)(&swT[s][d]);   // LDS.128, conflict-free
                acc[s] = fmaf(hv.x, w.x,
                         fmaf(hv.y, w.y,
                         fmaf(hv.z, w.z,
                         fmaf(hv.w, w.w, acc[s]))));
            }
        }

        // reduce across 64 threads: warp butterfly, then 2-warp combine
#pragma unroll
        for (int s = 0; s < NSLOT; ++s) {
            float v = acc[s];
#pragma unroll
            for (int off = 16; off; off >>= 1)
                v += __shfl_xor_sync(0xffffffffu, v, off);
            acc[s] = v;
        }
        if ((wtid & 31) == 0) {
#pragma unroll
            for (int s = 0; s < NSLOT; ++s) red[tok][wtid >> 5][s] = acc[s];
        }
        __syncthreads();
        if (wtid < 16) {
            int s = wtid;
            __half o;
            if (s < NSLOT) {
                float v = red[tok][0][s] + red[tok][1][s] + slot_b[s];
                o = __float2half_rn(tanhf(v));
            } else if (s == 8) {
                o = __float2half_rn(1.0f);
            } else {
                o = __float2half_rn(0.0f);
            }
            g_basis_h[(size_t)t * 16 + s] = o;
        }
    } else if (b < PREP_SLOTS_BLKS + PREP_SMAX_BLKS) {
        // ---- softmax (one row per thread)
        int r = (b - PREP_SLOTS_BLKS) * 256 + threadIdx.x;   // < 32768
        int w = r >> 3, l = r & 7;
        const float* row = logits + (size_t)r * 11;
        float x[11];
        float m = -1e30f;
#pragma unroll
        for (int c = 0; c < 11; ++c) { x[c] = row[c]; m = fmaxf(m, x[c]); }
        float sum = 0.0f;
#pragma unroll
        for (int c = 0; c < 11; ++c) { x[c] = __expf(x[c] - m); sum += x[c]; }
        float inv = 1.0f / sum;

        __half2* dst = (__half2*)(g_selB_h + ((size_t)l * NW + w) * 16);
#pragma unroll
        for (int c = 0; c < 4; ++c)
            dst[c] = __floats2half2_rn(x[2 * c] * inv, x[2 * c + 1] * inv);
        dst[4] = __floats2half2_rn((x[10] - x[8]) * inv, 0.0f);
        __half2 z = __floats2half2_rn(0.0f, 0.0f);
        dst[5] = z; dst[6] = z; dst[7] = z;
    } else {
        // ---- transpose tile
        int tb = b - (PREP_SLOTS_BLKS + PREP_SMAX_BLKS);
        int wt = tb >> 5;    // 0..127
        int dt = tb & 31;    // 0..31
        int tx = threadIdx.x & 31, ty = threadIdx.x >> 5;   // 32 x 8
#pragma unroll
        for (int i = 0; i < 4; ++i) {
            int w = wt * 32 + ty + i * 8;
            tsm[ty + i * 8][tx] = Wm[(size_t)w * DIM + dt * 32 + tx];
        }
        __syncthreads();
#pragma unroll
        for (int i = 0; i < 4; ++i) {
            int d = dt * 32 + ty + i * 8;
            g_outwT_h[(size_t)d * NW + wt * 32 + tx] = __float2half_rn(tsm[tx][ty + i * 8]);
        }
    }
}

// ---------------------------------------------------------------------------
// Kernel C: leaf einsum via mma.sync + f32 tree reduce.
// CTA: 128 tokens x 64 w (grid 64x32). 8 warps: warp_n = wid&3 (16 w),
// tgrp = wid>>2; 4 token tiles per warp. nt processed one at a time.
__global__ __launch_bounds__(256) void roots_mma_kernel(const float* __restrict__ node_params)
{
    __shared__ __align__(16) char sAraw[128 * 32];         // 128 tok rows x 32B
    __shared__ __align__(16) char sBraw[8 * 64 * 32];      // [leaf][w] rows x 32B

    const int tid  = threadIdx.x;
    const int lane = tid & 31;
    const int wid  = tid >> 5;
    const int warp_n = wid & 3;          // w tile (16 each)
    const int tgrp   = wid >> 2;         // 0/1
    const int bt = blockIdx.y * 128;
    const int bw = blockIdx.x * 64;

    const uint32_t uA = smem_u32(sAraw);
    const uint32_t uB = smem_u32(sBraw);

    // ---- fill sA: 256 chunks of 16B (one per thread), swizzle c ^ ((row>>2)&1)
    {
        int row = tid >> 1, c = tid & 1;
        const uint4 v = *(const uint4*)(g_basis_h + (size_t)(bt + row) * 16 + c * 8);
        *(uint4*)(sAraw + row * 32 + ((c ^ ((row >> 2) & 1)) << 4)) = v;
    }
    // ---- fill sB: 1024 chunks, 4 per thread
#pragma unroll
    for (int j = 0; j < 4; ++j) {
        int id = tid + 256 * j;
        int l = id >> 7, w = (id >> 1) & 63, c = id & 1;
        const uint4 v = *(const uint4*)(g_selB_h + ((size_t)l * NW + bw + w) * 16 + c * 8);
        *(uint4*)(sBraw + l * 2048 + w * 32 + ((c ^ ((w >> 2) & 1)) << 4)) = v;
    }
    __syncthreads();

    // ---- B fragments for all 8 leaves (kept in regs for whole CTA tile)
    uint32_t bfr[8][4];
    {
        int n  = warp_n * 16 + ((lane >> 4) & 1) * 8 + (lane & 7);
        int kc = (lane >> 3) & 1;
        uint32_t baddr = uB + n * 32 + ((kc ^ ((n >> 2) & 1)) << 4);
#pragma unroll
        for (int l = 0; l < 8; ++l)
            asm volatile("ldmatrix.sync.aligned.m8n8.x4.shared.b16 {%0,%1,%2,%3}, [%4];"
                         : "=r"(bfr[l][0]), "=r"(bfr[l][1]), "=r"(bfr[l][2]), "=r"(bfr[l][3])
                         : "r"(baddr + l * 2048));
    }

    float lw = __ldg(node_params + 0), rw = __ldg(node_params + 1);
    float pw = __ldg(node_params + 2), dw = __ldg(node_params + 3);
    float nb = __ldg(node_params + 4);
    float la = lw + dw, ra = rw - dw;

    const int g = lane >> 2, cq = lane & 3;

#pragma unroll
    for (int it = 0; it < 4; ++it) {
        const int m = tgrp + 2 * it;         // token tile 0..7

        uint32_t a[4];
        {
            int row = m * 16 + ((lane >> 3) & 1) * 8 + (lane & 7);
            int kc  = lane >> 4;
            uint32_t addr = uA + row * 32 + ((kc ^ ((row >> 2) & 1)) << 4);
            asm volatile("ldmatrix.sync.aligned.m8n8.x4.shared.b16 {%0,%1,%2,%3}, [%4];"
                         : "=r"(a[0]), "=r"(a[1]), "=r"(a[2]), "=r"(a[3]) : "r"(addr));
        }

#pragma unroll
        for (int nt = 0; nt < 2; ++nt) {
            float acc[8][4];
#pragma unroll
            for (int l = 0; l < 8; ++l)
#pragma unroll
                for (int i = 0; i < 4; ++i) acc[l][i] = 0.0f;

#pragma unroll
            for (int l = 0; l < 8; ++l)
                asm volatile(
                    "mma.sync.aligned.m16n8k16.row.col.f32.f16.f16.f32 "
                    "{%0,%1,%2,%3}, {%4,%5,%6,%7}, {%8,%9}, {%0,%1,%2,%3};"
                    : "+f"(acc[l][0]), "+f"(acc[l][1]), "+f"(acc[l][2]), "+f"(acc[l][3])
                    : "r"(a[0]), "r"(a[1]), "r"(a[2]), "r"(a[3]),
                      "r"(bfr[l][2 * nt]), "r"(bfr[l][2 * nt + 1]));

            float roots[4];
#pragma unroll
            for (int ci = 0; ci < 4; ++ci) {
                float x[8];
#pragma unroll
                for (int l = 0; l < 8; ++l) x[l] = acc[l][ci];
#pragma unroll
                for (int d = 0; d < 3; ++d) {
                    int n = NLEAF >> (d + 1);
#pragma unroll
                    for (int i = 0; i < 4; ++i) {
                        if (i < n) {
                            float L = x[2 * i], R = x[2 * i + 1];
                            x[i] = tanh_mufu(fmaf(L, fmaf(pw, R, la), fmaf(ra, R, nb)));
                        }
                    }
                }
                roots[ci] = x[0];
            }
            int col = bw + warp_n * 16 + nt * 8 + 2 * cq;
            int r0  = bt + m * 16 + g;
            *(__half2*)(g_roots_h + (size_t)r0 * NW + col)       = __floats2half2_rn(roots[0], roots[1]);
            *(__half2*)(g_roots_h + (size_t)(r0 + 8) * NW + col) = __floats2half2_rn(roots[2], roots[3]);
        }
    }
}

// ---------------------------------------------------------------------------
// Kernel D: fp16 mma.sync GEMM. 128x128x64 CTA tile, 4 warps of 64x64,
// 3-stage cp.async (96KB). Swizzle: chunk ^ (row&7); all row deltas are
// multiples of 8 so swizzle terms are loop-invariant.
#define BM 128
#define BN 128
#define BK 64
#define KTILES (NW / BK)                  // 64
#define ROWB (BK * 2)                     // 128 bytes/row
#define ASTG (BM * ROWB)                  // 16384
#define BSTG (BN * ROWB)                  // 16384
#define STG_BYTES (ASTG + BSTG)           // 32768
#define GSTAGES 3
#define GEMM_SMEM (GSTAGES * STG_BYTES)   // 98304

__device__ __forceinline__ void cp_async16(uint32_t dst, const void* src) {
    asm volatile("cp.async.cg.shared.global [%0], [%1], 16;" :: "r"(dst), "l"(src));
}

__global__ __launch_bounds__(128, 2) void gemm_mma_kernel(
    const float* __restrict__ bias, float* __restrict__ C)
{
    extern __shared__ char smem[];
    const uint32_t sbase = smem_u32(smem);

    const int tid  = threadIdx.x;
    const int lane = tid & 31;
    const int wid  = tid >> 5;
    const int warp_m = wid & 1;          // 64 rows each
    const int warp_n = wid >> 1;         // 64 cols each
    const int bm = blockIdx.y * BM;
    const int bn = blockIdx.x * BN;

    const __half* Ah = g_roots_h;
    const __half* Bh = g_outwT_h;

    const int row0 = tid >> 3, c0 = tid & 7;
    const int sw0  = c0 ^ (row0 & 7);
    const uint32_t dAbase = sbase + row0 * ROWB + sw0 * 16;
    const uint32_t dBbase = dAbase + ASTG;
    const __half* sAbase = Ah + (size_t)(bm + row0) * NW + c0 * 8;
    const __half* sBbase = Bh + (size_t)(bn + row0) * NW + c0 * 8;

    const int r7 = lane & 7;
    const uint32_t aRowBase = (uint32_t)((warp_m * 64 + ((lane >> 3) & 1) * 8 + r7) * ROWB);
    const uint32_t bRowBase = (uint32_t)(ASTG + (warp_n * 64 + ((lane >> 4) & 1) * 8 + r7) * ROWB);
    uint32_t kcA[4], kcB[4];
#pragma unroll
    for (int ks = 0; ks < 4; ++ks) {
        kcA[ks] = (uint32_t)(((ks * 2 + (lane >> 4)) ^ r7) << 4);
        kcB[ks] = (uint32_t)(((ks * 2 + ((lane >> 3) & 1)) ^ r7) << 4);
    }

    float acc[4][8][4];
#pragma unroll
    for (int mt = 0; mt < 4; ++mt)
#pragma unroll
        for (int nt = 0; nt < 8; ++nt)
#pragma unroll
            for (int i = 0; i < 4; ++i) acc[mt][nt][i] = 0.0f;

#pragma unroll
    for (int s = 0; s < GSTAGES - 1; ++s) {
#pragma unroll
        for (int j = 0; j < 8; ++j) {
            cp_async16(dAbase + s * STG_BYTES + j * 16 * ROWB,
                       sAbase + (size_t)j * 16 * NW + s * BK);
            cp_async16(dBbase + s * STG_BYTES + j * 16 * ROWB,
                       sBbase + (size_t)j * 16 * NW + s * BK);
        }
        asm volatile("cp.async.commit_group;" ::: "memory");
    }

    for (int kt = 0; kt < KTILES; ++kt) {
        asm volatile("cp.async.wait_group 1;" ::: "memory");
        __syncthreads();

        if (kt + 2 < KTILES) {
            int s = (kt + 2) % 3;
#pragma unroll
            for (int j = 0; j < 8; ++j) {
                cp_async16(dAbase + s * STG_BYTES + j * 16 * ROWB,
                           sAbase + (size_t)j * 16 * NW + (size_t)(kt + 2) * BK);
                cp_async16(dBbase + s * STG_BYTES + j * 16 * ROWB,
                           sBbase + (size_t)j * 16 * NW + (size_t)(kt + 2) * BK);
            }
        }
        asm volatile("cp.async.commit_group;" ::: "memory");

        const uint32_t so = sbase + (kt % 3) * STG_BYTES;
#pragma unroll
        for (int ks = 0; ks < 4; ++ks) {
            uint32_t a[4][4], b[8][2];
#pragma unroll
            for (int mt = 0; mt < 4; ++mt)
                asm volatile("ldmatrix.sync.aligned.m8n8.x4.shared.b16 {%0,%1,%2,%3}, [%4];"
                             : "=r"(a[mt][0]), "=r"(a[mt][1]), "=r"(a[mt][2]), "=r"(a[mt][3])
                             : "r"(so + aRowBase + mt * 16 * ROWB + kcA[ks]));
#pragma unroll
            for (int p = 0; p < 4; ++p)
                asm volatile("ldmatrix.sync.aligned.m8n8.x4.shared.b16 {%0,%1,%2,%3}, [%4];"
                             : "=r"(b[2 * p][0]), "=r"(b[2 * p][1]),
                               "=r"(b[2 * p + 1][0]), "=r"(b[2 * p + 1][1])
                             : "r"(so + bRowBase + p * 16 * ROWB + kcB[ks]));
#pragma unroll
            for (int mt = 0; mt < 4; ++mt)
#pragma unroll
                for (int nt = 0; nt < 8; ++nt)
                    asm volatile(
                        "mma.sync.aligned.m16n8k16.row.col.f32.f16.f16.f32 "
                        "{%0,%1,%2,%3}, {%4,%5,%6,%7}, {%8,%9}, {%0,%1,%2,%3};"
                        : "+f"(acc[mt][nt][0]), "+f"(acc[mt][nt][1]),
                          "+f"(acc[mt][nt][2]), "+f"(acc[mt][nt][3])
                        : "r"(a[mt][0]), "r"(a[mt][1]), "r"(a[mt][2]), "r"(a[mt][3]),
                          "r"(b[nt][0]), "r"(b[nt][1]));
        }
    }

    const int g = lane >> 2, cq = lane & 3;
#pragma unroll
    for (int mt = 0; mt < 4; ++mt) {
        int r0 = bm + warp_m * 64 + mt * 16 + g;
#pragma unroll
        for (int nt = 0; nt < 8; ++nt) {
            int col = bn + warp_n * 64 + nt * 8 + 2 * cq;
            float2 bb = *(const float2*)(bias + col);
            float2 v0 = make_float2(acc[mt][nt][0] + bb.x, acc[mt][nt][1] + bb.y);
            float2 v1 = make_float2(acc[mt][nt][2] + bb.x, acc[mt][nt][3] + bb.y);
            *(float2*)(C + (size_t)r0 * DIM + col) = v0;
            *(float2*)(C + (size_t)(r0 + 8) * DIM + col) = v1;
        }
    }
}

// ---------------------------------------------------------------------------
extern "C" void kernel_launch(void* const* d_in, const int* in_sizes, int n_in,
                              void* d_out, int out_size)
{
    const float* hidden      = (const float*)d_in[0];
    const float* slot_w      = (const float*)d_in[1];
    const float* slot_b      = (const float*)d_in[2];
    const float* leaf_logits = (const float*)d_in[3];
    const float* node_params = (const float*)d_in[4];
    const float* out_w       = (const float*)d_in[5];
    const float* out_b       = (const float*)d_in[6];
    float* out = (float*)d_out;

    cudaFuncSetAttribute(gemm_mma_kernel,
                         cudaFuncAttributeMaxDynamicSharedMemorySize, GEMM_SMEM);

    prep_kernel<<<PREP_BLKS, 256>>>(hidden, slot_w, slot_b, leaf_logits, out_w);
    roots_mma_kernel<<<dim3(NW / 64, T_TOK / 128), 256>>>(node_params);
    gemm_mma_kernel<<<dim3(DIM / BN, T_TOK / BM), 128, GEMM_SMEM>>>(out_b, out);
}